// round 1
// baseline (speedup 1.0000x reference)
#include <cuda_runtime.h>
#include <cuda_bf16.h>
#include <math.h>

// Problem constants
#define BB   32
#define SS   2048
#define EE   512
#define NCc  128
#define NTt  32
#define HH   8
#define QQ   4

// ---------------- device scratch (no allocations allowed) ----------------
__device__ float g_boxA [BB * 3 * EE];          // [head_emb | body_emb | box_op_e]
__device__ float g_lstmA[BB * 3 * EE];          // [encoded_box | att | h0]
__device__ float g_gates[BB * 4 * EE];
__device__ float g_hc   [BB * 2 * EE];          // [h | ctx]
__device__ float g_scores[BB * SS];
__device__ float g_attw  [BB * SS];
#define NCHUNK 32
__device__ float g_part[BB * NCHUNK * EE];      // ctx partials
__device__ int   g_mask_mode;                   // 0=int32, 1=float32, 2=uint8

// ---------------- mask dtype sniffer ----------------
__global__ void detect_mask_kernel(const unsigned int* w, int nwords) {
    __shared__ int s_ok32, s_okf;
    if (threadIdx.x == 0) { s_ok32 = 1; s_okf = 1; }
    __syncthreads();
    int ok32 = 1, okf = 1;
    for (int i = threadIdx.x; i < nwords; i += blockDim.x) {
        unsigned v = w[i];
        if (v > 1u) ok32 = 0;
        if (v != 0u && v != 0x3F800000u) okf = 0;
    }
    if (!ok32) atomicAnd(&s_ok32, 0);
    if (!okf)  atomicAnd(&s_okf, 0);
    __syncthreads();
    if (threadIdx.x == 0) g_mask_mode = s_ok32 ? 0 : (s_okf ? 1 : 2);
}

// ---------------- gather / concat prep ----------------
__global__ void prep_kernel(const float* __restrict__ agg_emb,
                            const float* __restrict__ encoded_col,
                            const float* __restrict__ encoded_tab,
                            const float* __restrict__ box_op_emb,
                            const int* __restrict__ head_agg,
                            const int* __restrict__ head_col,
                            const int* __restrict__ quant_tab,
                            const int* __restrict__ box_op,
                            const float* __restrict__ att,
                            const float* __restrict__ h0) {
    int b = blockIdx.x;
    int e = threadIdx.x;                 // 512 threads
    __shared__ int ia[HH], ic[HH], iq[QQ], ib;
    if (e < HH) ia[e] = head_agg[b * HH + e];
    else if (e < 2 * HH) ic[e - HH] = head_col[b * HH + (e - HH)];
    else if (e < 2 * HH + QQ) iq[e - 2 * HH] = quant_tab[b * QQ + (e - 2 * HH)];
    else if (e == 2 * HH + QQ) ib = box_op[b];
    __syncthreads();

    float he = 0.f;
#pragma unroll
    for (int h = 0; h < HH; h++)
        he += agg_emb[ia[h] * EE + e] + encoded_col[((size_t)b * NCc + ic[h]) * EE + e];
    he *= (1.0f / HH);
    float be = 0.f;
#pragma unroll
    for (int q = 0; q < QQ; q++)
        be += encoded_tab[((size_t)b * NTt + iq[q]) * EE + e];
    be *= (1.0f / QQ);

    float* boxA = g_boxA + (size_t)b * 3 * EE;
    boxA[e]          = he;
    boxA[EE + e]     = be;
    boxA[2 * EE + e] = box_op_emb[ib * EE + e];

    float* lA = g_lstmA + (size_t)b * 3 * EE;
    lA[EE + e]     = att[b * EE + e];
    lA[2 * EE + e] = h0[b * EE + e];
}

// ---------------- batched small GEMM: C[32,N] = act(A[32,K] @ W^T + bias) ----------------
// W is split: columns k<K1 come from W1 (row stride K1), rest from W2 (row stride K-K1)
__global__ void gemm32_kernel(const float* __restrict__ A, int K,
                              const float* __restrict__ W1, int K1,
                              const float* __restrict__ W2,
                              const float* __restrict__ bias1,
                              const float* __restrict__ bias2,
                              float* __restrict__ C, int ldc, int relu) {
    __shared__ float As[32][33];
    __shared__ float Ws[64][33];
    int tid = threadIdx.x;               // 256
    int n0  = blockIdx.x * 64;
    int tn  = tid & 15;                  // 4 n's each
    int tb  = tid >> 4;                  // b and b+16
    float acc[2][4] = {};
    int K2len = K - K1;

    for (int k0 = 0; k0 < K; k0 += 32) {
#pragma unroll
        for (int i = 0; i < 4; i++) {
            int idx = tid + i * 256;
            int r = idx >> 5, kk = idx & 31;
            As[r][kk] = A[(size_t)r * K + k0 + kk];
        }
#pragma unroll
        for (int i = 0; i < 8; i++) {
            int idx = tid + i * 256;
            int n = idx >> 5, kk = idx & 31;
            int kg = k0 + kk;
            float wv = (kg < K1) ? W1[(size_t)(n0 + n) * K1 + kg]
                                 : W2[(size_t)(n0 + n) * K2len + (kg - K1)];
            Ws[n][kk] = wv;
        }
        __syncthreads();
#pragma unroll
        for (int kk = 0; kk < 32; kk++) {
            float a0 = As[tb][kk];
            float a1 = As[tb + 16][kk];
#pragma unroll
            for (int j = 0; j < 4; j++) {
                float wv = Ws[tn * 4 + j][kk];
                acc[0][j] = fmaf(a0, wv, acc[0][j]);
                acc[1][j] = fmaf(a1, wv, acc[1][j]);
            }
        }
        __syncthreads();
    }
#pragma unroll
    for (int j = 0; j < 4; j++) {
        int n = n0 + tn * 4 + j;
        float bb = bias1[n] + (bias2 ? bias2[n] : 0.f);
        float v0 = acc[0][j] + bb;
        float v1 = acc[1][j] + bb;
        if (relu) { v0 = fmaxf(v0, 0.f); v1 = fmaxf(v1, 0.f); }
        C[(size_t)tb * ldc + n]        = v0;
        C[(size_t)(tb + 16) * ldc + n] = v1;
    }
}

// ---------------- LSTM elementwise ----------------
__device__ __forceinline__ float sigmf(float x) { return 1.0f / (1.0f + expf(-x)); }

__global__ void lstm_elem_kernel(const float* __restrict__ c0) {
    int idx = blockIdx.x * blockDim.x + threadIdx.x;   // 32*512
    int b = idx >> 9, e = idx & 511;
    const float* g = g_gates + (size_t)b * 4 * EE;
    float gi = g[e], gf = g[EE + e], gg = g[2 * EE + e], go = g[3 * EE + e];
    float c = sigmf(gf) * c0[b * EE + e] + sigmf(gi) * tanhf(gg);
    float h = sigmf(go) * tanhf(c);
    g_hc[(size_t)b * 2 * EE + e] = h;
}

// ---------------- attention scores: warp per source row ----------------
__global__ void scores_kernel(const float* __restrict__ src_att,
                              const void* __restrict__ maskp) {
    int b = blockIdx.y;
    int tid = threadIdx.x;               // 256 = 8 warps
    __shared__ __align__(16) float sh[EE];
    for (int i = tid; i < EE; i += 256) sh[i] = g_hc[(size_t)b * 2 * EE + i];
    __syncthreads();

    int warp = tid >> 5, lane = tid & 31;
    int s = blockIdx.x * 8 + warp;
    const float4* row = (const float4*)(src_att + ((size_t)b * SS + s) * EE);
    const float4* h4  = (const float4*)sh;
    float a0 = 0.f, a1 = 0.f, a2 = 0.f, a3 = 0.f;
    float4 v0 = row[lane +  0], h0v = h4[lane +  0];
    float4 v1 = row[lane + 32], h1v = h4[lane + 32];
    float4 v2 = row[lane + 64], h2v = h4[lane + 64];
    float4 v3 = row[lane + 96], h3v = h4[lane + 96];
    a0 = v0.x * h0v.x + v0.y * h0v.y + v0.z * h0v.z + v0.w * h0v.w;
    a1 = v1.x * h1v.x + v1.y * h1v.y + v1.z * h1v.z + v1.w * h1v.w;
    a2 = v2.x * h2v.x + v2.y * h2v.y + v2.z * h2v.z + v2.w * h2v.w;
    a3 = v3.x * h3v.x + v3.y * h3v.y + v3.z * h3v.z + v3.w * h3v.w;
    float acc = (a0 + a1) + (a2 + a3);
#pragma unroll
    for (int off = 16; off > 0; off >>= 1)
        acc += __shfl_xor_sync(0xFFFFFFFF, acc, off);

    if (lane == 0) {
        int mm = g_mask_mode;
        bool masked;
        size_t mi = (size_t)b * SS + s;
        if (mm == 0)      masked = ((const int*)maskp)[mi] != 0;
        else if (mm == 1) masked = ((const float*)maskp)[mi] != 0.f;
        else              masked = ((const unsigned char*)maskp)[mi] != 0;
        g_scores[mi] = masked ? -INFINITY : acc;
    }
}

// ---------------- softmax over S per batch row ----------------
__global__ void softmax_kernel() {
    int b = blockIdx.x;
    int tid = threadIdx.x;               // 256
    const float* sc = g_scores + (size_t)b * SS;
    __shared__ float red[256];
    float m = -INFINITY;
    for (int s = tid; s < SS; s += 256) m = fmaxf(m, sc[s]);
    red[tid] = m; __syncthreads();
    for (int o = 128; o > 0; o >>= 1) { if (tid < o) red[tid] = fmaxf(red[tid], red[tid + o]); __syncthreads(); }
    float mx = red[0]; __syncthreads();
    float sum = 0.f;
    for (int s = tid; s < SS; s += 256) sum += expf(sc[s] - mx);
    red[tid] = sum; __syncthreads();
    for (int o = 128; o > 0; o >>= 1) { if (tid < o) red[tid] += red[tid + o]; __syncthreads(); }
    float inv = 1.0f / red[0];
    float* w = g_attw + (size_t)b * SS;
    for (int s = tid; s < SS; s += 256) w[s] = expf(sc[s] - mx) * inv;
}

// ---------------- ctx partials: block per (chunk, b) ----------------
__global__ void ctx_part_kernel(const float* __restrict__ src) {
    int ch = blockIdx.x, b = blockIdx.y;
    int tid = threadIdx.x;               // 128, each owns float4 of E
    const int ROWS = SS / NCHUNK;        // 64
    __shared__ float w[ROWS];
    if (tid < ROWS) w[tid] = g_attw[(size_t)b * SS + ch * ROWS + tid];
    __syncthreads();
    const float4* base = (const float4*)(src + ((size_t)b * SS + (size_t)ch * ROWS) * EE);
    float4 acc = make_float4(0.f, 0.f, 0.f, 0.f);
#pragma unroll 8
    for (int s = 0; s < ROWS; s++) {
        float4 v = base[(size_t)s * 128 + tid];
        float ws = w[s];
        acc.x = fmaf(ws, v.x, acc.x);
        acc.y = fmaf(ws, v.y, acc.y);
        acc.z = fmaf(ws, v.z, acc.z);
        acc.w = fmaf(ws, v.w, acc.w);
    }
    ((float4*)g_part)[((size_t)b * NCHUNK + ch) * 128 + tid] = acc;
}

// ---------------- reduce partials into g_hc[:, E:] ----------------
__global__ void ctx_reduce_kernel() {
    int idx = blockIdx.x * blockDim.x + threadIdx.x;   // 32*512
    int b = idx >> 9, e = idx & 511;
    float s = 0.f;
#pragma unroll
    for (int c = 0; c < NCHUNK; c++)
        s += g_part[((size_t)b * NCHUNK + c) * EE + e];
    g_hc[(size_t)b * 2 * EE + EE + e] = s;
}

// ---------------- launch ----------------
extern "C" void kernel_launch(void* const* d_in, const int* in_sizes, int n_in,
                              void* d_out, int out_size) {
    const float* encoded_src     = (const float*)d_in[0];
    const float* encoded_src_att = (const float*)d_in[1];
    const float* encoded_col     = (const float*)d_in[2];
    const float* encoded_tab     = (const float*)d_in[3];
    const void*  src_mask        = d_in[4];
    const float* att             = (const float*)d_in[5];
    const float* h0              = (const float*)d_in[6];
    const float* c0              = (const float*)d_in[7];
    const int*   head_agg        = (const int*)d_in[8];
    const int*   head_col        = (const int*)d_in[9];
    const int*   quant_tab       = (const int*)d_in[10];
    const int*   box_op          = (const int*)d_in[11];
    const float* agg_emb         = (const float*)d_in[12];
    const float* box_op_emb      = (const float*)d_in[13];
    const float* W_box           = (const float*)d_in[14];
    const float* b_box           = (const float*)d_in[15];
    const float* W_ih            = (const float*)d_in[16];
    const float* W_hh            = (const float*)d_in[17];
    const float* b_ih            = (const float*)d_in[18];
    const float* b_hh            = (const float*)d_in[19];
    const float* W_att           = (const float*)d_in[20];
    const float* b_att           = (const float*)d_in[21];
    float* out = (float*)d_out;

    float *p_boxA, *p_lstmA, *p_gates, *p_hc;
    cudaGetSymbolAddress((void**)&p_boxA, g_boxA);
    cudaGetSymbolAddress((void**)&p_lstmA, g_lstmA);
    cudaGetSymbolAddress((void**)&p_gates, g_gates);
    cudaGetSymbolAddress((void**)&p_hc, g_hc);

    // 1. sniff mask dtype (scan first 64KB of buffer, valid for all candidates)
    detect_mask_kernel<<<1, 256>>>((const unsigned int*)src_mask, (BB * SS) / 4);

    // 2. gathers + concat prep
    prep_kernel<<<BB, EE>>>(agg_emb, encoded_col, encoded_tab, box_op_emb,
                            head_agg, head_col, quant_tab, box_op, att, h0);

    // 3. encoded_box = relu(boxA @ W_box^T + b_box) -> g_lstmA[:, :E]
    gemm32_kernel<<<EE / 64, 256>>>(p_boxA, 3 * EE, W_box, 3 * EE, nullptr,
                                    b_box, nullptr, p_lstmA, 3 * EE, 1);

    // 4. gates = [box|att|h0] @ [W_ih|W_hh]^T + b_ih + b_hh
    gemm32_kernel<<<(4 * EE) / 64, 256>>>(p_lstmA, 3 * EE, W_ih, 2 * EE, W_hh,
                                          b_ih, b_hh, p_gates, 4 * EE, 0);

    // 5. LSTM elementwise -> h into g_hc[:, :E]
    lstm_elem_kernel<<<(BB * EE) / 256, 256>>>(c0);

    // 6. attention scores (134 MB stream)
    scores_kernel<<<dim3(SS / 8, BB), 256>>>(encoded_src_att, src_mask);

    // 7. softmax
    softmax_kernel<<<BB, 256>>>();

    // 8. ctx partials (134 MB stream)
    ctx_part_kernel<<<dim3(NCHUNK, BB), 128>>>(encoded_src);

    // 9. reduce -> g_hc[:, E:]
    ctx_reduce_kernel<<<(BB * EE) / 256, 256>>>();

    // 10. att_new = relu([h|ctx] @ W_att^T + b_att) -> d_out
    gemm32_kernel<<<EE / 64, 256>>>(p_hc, 2 * EE, W_att, 2 * EE, nullptr,
                                    b_att, nullptr, out, EE, 1);
}

// round 2
// speedup vs baseline: 1.9011x; 1.9011x over previous
#include <cuda_runtime.h>
#include <cuda_bf16.h>
#include <math.h>

// Problem constants
#define BB   32
#define SS   2048
#define EE   512
#define NCc  128
#define NTt  32
#define HH   8
#define QQ   4

// ---------------- device scratch (no allocations allowed) ----------------
__device__ float g_boxA [BB * 3 * EE];          // [head_emb | body_emb | box_op_e]
__device__ float g_lstmA[BB * 3 * EE];          // [encoded_box | att | h0]
__device__ float g_gates[BB * 4 * EE];
__device__ float g_hc   [BB * 2 * EE];          // [h | ctx]
__device__ float g_scores[BB * SS];
__device__ float g_attw  [BB * SS];
#define NCHUNK 32
__device__ float g_part[BB * NCHUNK * EE];      // ctx partials
__device__ int   g_mask_mode;                   // 0=int32, 1=float32, 2=uint8

// ---------------- mask dtype sniffer (small scan, single block) ----------------
__global__ void detect_mask_kernel(const unsigned int* w, int nwords) {
    __shared__ int s_ok32, s_okf;
    if (threadIdx.x == 0) { s_ok32 = 1; s_okf = 1; }
    __syncthreads();
    int ok32 = 1, okf = 1;
    for (int i = threadIdx.x; i < nwords; i += blockDim.x) {
        unsigned v = w[i];
        if (v > 1u) ok32 = 0;
        if (v != 0u && v != 0x3F800000u) okf = 0;
    }
    if (!ok32) atomicAnd(&s_ok32, 0);
    if (!okf)  atomicAnd(&s_okf, 0);
    __syncthreads();
    if (threadIdx.x == 0) g_mask_mode = s_ok32 ? 0 : (s_okf ? 1 : 2);
}

// ---------------- gather / concat prep ----------------
__global__ void prep_kernel(const float* __restrict__ agg_emb,
                            const float* __restrict__ encoded_col,
                            const float* __restrict__ encoded_tab,
                            const float* __restrict__ box_op_emb,
                            const int* __restrict__ head_agg,
                            const int* __restrict__ head_col,
                            const int* __restrict__ quant_tab,
                            const int* __restrict__ box_op,
                            const float* __restrict__ att,
                            const float* __restrict__ h0) {
    int b = blockIdx.x;
    int e = threadIdx.x;                 // 512 threads
    __shared__ int ia[HH], ic[HH], iq[QQ], ib;
    if (e < HH) ia[e] = head_agg[b * HH + e];
    else if (e < 2 * HH) ic[e - HH] = head_col[b * HH + (e - HH)];
    else if (e < 2 * HH + QQ) iq[e - 2 * HH] = quant_tab[b * QQ + (e - 2 * HH)];
    else if (e == 2 * HH + QQ) ib = box_op[b];
    __syncthreads();

    float he = 0.f;
#pragma unroll
    for (int h = 0; h < HH; h++)
        he += agg_emb[ia[h] * EE + e] + encoded_col[((size_t)b * NCc + ic[h]) * EE + e];
    he *= (1.0f / HH);
    float be = 0.f;
#pragma unroll
    for (int q = 0; q < QQ; q++)
        be += encoded_tab[((size_t)b * NTt + iq[q]) * EE + e];
    be *= (1.0f / QQ);

    float* boxA = g_boxA + (size_t)b * 3 * EE;
    boxA[e]          = he;
    boxA[EE + e]     = be;
    boxA[2 * EE + e] = box_op_emb[ib * EE + e];

    float* lA = g_lstmA + (size_t)b * 3 * EE;
    lA[EE + e]     = att[b * EE + e];
    lA[2 * EE + e] = h0[b * EE + e];
}

// ---------------- warp-per-row GEMM: C[32,N] = act(A[32,K] @ W^T + bias) ----
// One warp owns output column n; lane = batch b. A is staged transposed in
// shared (K-tiled). Weights are read coalesced once, broadcast via shfl.
// W columns k<K1 from W1 (row stride K1), rest from W2 (row stride K-K1).
#define KT 256
__global__ void gemmv_kernel(const float* __restrict__ A, int K,
                             const float* __restrict__ W1, int K1,
                             const float* __restrict__ W2,
                             const float* __restrict__ bias1,
                             const float* __restrict__ bias2,
                             float* __restrict__ C, int ldc, int relu) {
    __shared__ float At[KT][33];
    int tid  = threadIdx.x;              // 256 = 8 warps
    int warp = tid >> 5, lane = tid & 31;
    int n = blockIdx.x * 8 + warp;
    int K2len = K - K1;
    float acc = 0.f;

    for (int k0 = 0; k0 < K; k0 += KT) {
        // stage A tile transposed: At[k][b] = A[b][k0+k]; coalesced over k
#pragma unroll
        for (int i = 0; i < (KT * 32) / 256; i++) {
            int idx = tid + i * 256;     // idx = b*KT + k
            int b = idx >> 8;            // KT == 256
            int k = idx & (KT - 1);
            At[k][b] = A[(size_t)b * K + k0 + k];
        }
        __syncthreads();

#pragma unroll 2
        for (int k = 0; k < KT; k += 32) {
            int kg = k0 + k + lane;
            float w = (kg < K1) ? W1[(size_t)n * K1 + kg]
                                : W2[(size_t)n * K2len + (kg - K1)];
#pragma unroll
            for (int kk = 0; kk < 32; kk++) {
                float wv = __shfl_sync(0xFFFFFFFF, w, kk);
                acc = fmaf(wv, At[k + kk][lane], acc);
            }
        }
        __syncthreads();
    }

    float bb = bias1[n] + (bias2 ? bias2[n] : 0.f);
    float v = acc + bb;
    if (relu) v = fmaxf(v, 0.f);
    C[(size_t)lane * ldc + n] = v;       // lane = batch
}

// ---------------- LSTM elementwise ----------------
__device__ __forceinline__ float sigmf(float x) { return 1.0f / (1.0f + expf(-x)); }

__global__ void lstm_elem_kernel(const float* __restrict__ c0) {
    int idx = blockIdx.x * blockDim.x + threadIdx.x;   // 32*512
    int b = idx >> 9, e = idx & 511;
    const float* g = g_gates + (size_t)b * 4 * EE;
    float gi = g[e], gf = g[EE + e], gg = g[2 * EE + e], go = g[3 * EE + e];
    float c = sigmf(gf) * c0[b * EE + e] + sigmf(gi) * tanhf(gg);
    float h = sigmf(go) * tanhf(c);
    g_hc[(size_t)b * 2 * EE + e] = h;
}

// ---------------- attention scores: warp per source row ----------------
__global__ void scores_kernel(const float* __restrict__ src_att,
                              const void* __restrict__ maskp) {
    int b = blockIdx.y;
    int tid = threadIdx.x;               // 256 = 8 warps
    __shared__ __align__(16) float sh[EE];
    for (int i = tid; i < EE; i += 256) sh[i] = g_hc[(size_t)b * 2 * EE + i];
    __syncthreads();

    int warp = tid >> 5, lane = tid & 31;
    int s = blockIdx.x * 8 + warp;
    const float4* row = (const float4*)(src_att + ((size_t)b * SS + s) * EE);
    const float4* h4  = (const float4*)sh;
    float4 v0 = row[lane +  0], h0v = h4[lane +  0];
    float4 v1 = row[lane + 32], h1v = h4[lane + 32];
    float4 v2 = row[lane + 64], h2v = h4[lane + 64];
    float4 v3 = row[lane + 96], h3v = h4[lane + 96];
    float a0 = v0.x * h0v.x + v0.y * h0v.y + v0.z * h0v.z + v0.w * h0v.w;
    float a1 = v1.x * h1v.x + v1.y * h1v.y + v1.z * h1v.z + v1.w * h1v.w;
    float a2 = v2.x * h2v.x + v2.y * h2v.y + v2.z * h2v.z + v2.w * h2v.w;
    float a3 = v3.x * h3v.x + v3.y * h3v.y + v3.z * h3v.z + v3.w * h3v.w;
    float acc = (a0 + a1) + (a2 + a3);
#pragma unroll
    for (int off = 16; off > 0; off >>= 1)
        acc += __shfl_xor_sync(0xFFFFFFFF, acc, off);

    if (lane == 0) {
        int mm = g_mask_mode;
        bool masked;
        size_t mi = (size_t)b * SS + s;
        if (mm == 0)      masked = ((const int*)maskp)[mi] != 0;
        else if (mm == 1) masked = ((const float*)maskp)[mi] != 0.f;
        else              masked = ((const unsigned char*)maskp)[mi] != 0;
        g_scores[mi] = masked ? -INFINITY : acc;
    }
}

// ---------------- softmax over S per batch row ----------------
__global__ void softmax_kernel() {
    int b = blockIdx.x;
    int tid = threadIdx.x;               // 256
    const float* sc = g_scores + (size_t)b * SS;
    __shared__ float red[256];
    float m = -INFINITY;
    for (int s = tid; s < SS; s += 256) m = fmaxf(m, sc[s]);
    red[tid] = m; __syncthreads();
    for (int o = 128; o > 0; o >>= 1) { if (tid < o) red[tid] = fmaxf(red[tid], red[tid + o]); __syncthreads(); }
    float mx = red[0]; __syncthreads();
    float sum = 0.f;
    for (int s = tid; s < SS; s += 256) sum += expf(sc[s] - mx);
    red[tid] = sum; __syncthreads();
    for (int o = 128; o > 0; o >>= 1) { if (tid < o) red[tid] += red[tid + o]; __syncthreads(); }
    float inv = 1.0f / red[0];
    float* w = g_attw + (size_t)b * SS;
    for (int s = tid; s < SS; s += 256) w[s] = expf(sc[s] - mx) * inv;
}

// ---------------- ctx partials: block per (chunk, b) ----------------
__global__ void ctx_part_kernel(const float* __restrict__ src) {
    int ch = blockIdx.x, b = blockIdx.y;
    int tid = threadIdx.x;               // 128, each owns float4 of E
    const int ROWS = SS / NCHUNK;        // 64
    __shared__ float w[ROWS];
    if (tid < ROWS) w[tid] = g_attw[(size_t)b * SS + ch * ROWS + tid];
    __syncthreads();
    const float4* base = (const float4*)(src + ((size_t)b * SS + (size_t)ch * ROWS) * EE);
    float4 acc = make_float4(0.f, 0.f, 0.f, 0.f);
#pragma unroll 8
    for (int s = 0; s < ROWS; s++) {
        float4 v = base[(size_t)s * 128 + tid];
        float ws = w[s];
        acc.x = fmaf(ws, v.x, acc.x);
        acc.y = fmaf(ws, v.y, acc.y);
        acc.z = fmaf(ws, v.z, acc.z);
        acc.w = fmaf(ws, v.w, acc.w);
    }
    ((float4*)g_part)[((size_t)b * NCHUNK + ch) * 128 + tid] = acc;
}

// ---------------- reduce partials into g_hc[:, E:] ----------------
__global__ void ctx_reduce_kernel() {
    int idx = blockIdx.x * blockDim.x + threadIdx.x;   // 32*512
    int b = idx >> 9, e = idx & 511;
    float s = 0.f;
#pragma unroll
    for (int c = 0; c < NCHUNK; c++)
        s += g_part[((size_t)b * NCHUNK + c) * EE + e];
    g_hc[(size_t)b * 2 * EE + EE + e] = s;
}

// ---------------- launch ----------------
extern "C" void kernel_launch(void* const* d_in, const int* in_sizes, int n_in,
                              void* d_out, int out_size) {
    const float* encoded_src     = (const float*)d_in[0];
    const float* encoded_src_att = (const float*)d_in[1];
    const float* encoded_col     = (const float*)d_in[2];
    const float* encoded_tab     = (const float*)d_in[3];
    const void*  src_mask        = d_in[4];
    const float* att             = (const float*)d_in[5];
    const float* h0              = (const float*)d_in[6];
    const float* c0              = (const float*)d_in[7];
    const int*   head_agg        = (const int*)d_in[8];
    const int*   head_col        = (const int*)d_in[9];
    const int*   quant_tab       = (const int*)d_in[10];
    const int*   box_op          = (const int*)d_in[11];
    const float* agg_emb         = (const float*)d_in[12];
    const float* box_op_emb      = (const float*)d_in[13];
    const float* W_box           = (const float*)d_in[14];
    const float* b_box           = (const float*)d_in[15];
    const float* W_ih            = (const float*)d_in[16];
    const float* W_hh            = (const float*)d_in[17];
    const float* b_ih            = (const float*)d_in[18];
    const float* b_hh            = (const float*)d_in[19];
    const float* W_att           = (const float*)d_in[20];
    const float* b_att           = (const float*)d_in[21];
    float* out = (float*)d_out;

    float *p_boxA, *p_lstmA, *p_gates, *p_hc;
    cudaGetSymbolAddress((void**)&p_boxA, g_boxA);
    cudaGetSymbolAddress((void**)&p_lstmA, g_lstmA);
    cudaGetSymbolAddress((void**)&p_gates, g_gates);
    cudaGetSymbolAddress((void**)&p_hc, g_hc);

    // 1. sniff mask dtype (8KB scan — statistically sufficient for random mask)
    detect_mask_kernel<<<1, 256>>>((const unsigned int*)src_mask, 2048);

    // 2. gathers + concat prep
    prep_kernel<<<BB, EE>>>(agg_emb, encoded_col, encoded_tab, box_op_emb,
                            head_agg, head_col, quant_tab, box_op, att, h0);

    // 3. encoded_box = relu(boxA @ W_box^T + b_box) -> g_lstmA[:, :E]
    gemmv_kernel<<<EE / 8, 256>>>(p_boxA, 3 * EE, W_box, 3 * EE, nullptr,
                                  b_box, nullptr, p_lstmA, 3 * EE, 1);

    // 4. gates = [box|att|h0] @ [W_ih|W_hh]^T + b_ih + b_hh
    gemmv_kernel<<<(4 * EE) / 8, 256>>>(p_lstmA, 3 * EE, W_ih, 2 * EE, W_hh,
                                        b_ih, b_hh, p_gates, 4 * EE, 0);

    // 5. LSTM elementwise -> h into g_hc[:, :E]
    lstm_elem_kernel<<<(BB * EE) / 256, 256>>>(c0);

    // 6. attention scores (134 MB stream)
    scores_kernel<<<dim3(SS / 8, BB), 256>>>(encoded_src_att, src_mask);

    // 7. softmax
    softmax_kernel<<<BB, 256>>>();

    // 8. ctx partials (134 MB stream)
    ctx_part_kernel<<<dim3(NCHUNK, BB), 128>>>(encoded_src);

    // 9. reduce -> g_hc[:, E:]
    ctx_reduce_kernel<<<(BB * EE) / 256, 256>>>();

    // 10. att_new = relu([h|ctx] @ W_att^T + b_att) -> d_out
    gemmv_kernel<<<EE / 8, 256>>>(p_hc, 2 * EE, W_att, 2 * EE, nullptr,
                                  b_att, nullptr, out, EE, 1);
}

// round 3
// speedup vs baseline: 2.4020x; 1.2635x over previous
#include <cuda_runtime.h>
#include <cuda_bf16.h>
#include <math.h>

// Problem constants
#define BB   32
#define SS   2048
#define EE   512
#define NCc  128
#define NTt  32
#define HH   8
#define QQ   4

// split-K chunk counts
#define CH_BOX   12
#define CH_GATES 12
#define CH_ATT   16

// ---------------- device scratch (no allocations allowed) ----------------
__device__ float g_boxA [BB * 3 * EE];          // [head_emb | body_emb | box_op_e]
__device__ float g_lstmA[BB * 3 * EE];          // [encoded_box | att | h0]
__device__ float g_hc   [BB * 2 * EE];          // [h | ctx]
__device__ float g_scores[BB * SS];
__device__ float g_attw  [BB * SS];
#define NCHUNK 32
__device__ float g_part   [BB * NCHUNK * EE];        // ctx partials
__device__ float g_pbox   [CH_BOX   * BB * EE];      // box gemm partials
__device__ float g_pgates [CH_GATES * BB * 4 * EE];  // gates gemm partials
__device__ float g_patt   [CH_ATT   * BB * EE];      // att gemm partials
__device__ int   g_mask_mode;                        // 0=int32, 1=float32, 2=uint8

// ---------------- mask dtype sniffer (small scan, single block) ----------------
__global__ void detect_mask_kernel(const unsigned int* w, int nwords) {
    __shared__ int s_ok32, s_okf;
    if (threadIdx.x == 0) { s_ok32 = 1; s_okf = 1; }
    __syncthreads();
    int ok32 = 1, okf = 1;
    for (int i = threadIdx.x; i < nwords; i += blockDim.x) {
        unsigned v = w[i];
        if (v > 1u) ok32 = 0;
        if (v != 0u && v != 0x3F800000u) okf = 0;
    }
    if (!ok32) atomicAnd(&s_ok32, 0);
    if (!okf)  atomicAnd(&s_okf, 0);
    __syncthreads();
    if (threadIdx.x == 0) g_mask_mode = s_ok32 ? 0 : (s_okf ? 1 : 2);
}

// ---------------- gather / concat prep ----------------
__global__ void prep_kernel(const float* __restrict__ agg_emb,
                            const float* __restrict__ encoded_col,
                            const float* __restrict__ encoded_tab,
                            const float* __restrict__ box_op_emb,
                            const int* __restrict__ head_agg,
                            const int* __restrict__ head_col,
                            const int* __restrict__ quant_tab,
                            const int* __restrict__ box_op,
                            const float* __restrict__ att,
                            const float* __restrict__ h0) {
    int b = blockIdx.x;
    int e = threadIdx.x;                 // 512 threads
    __shared__ int ia[HH], ic[HH], iq[QQ], ib;
    if (e < HH) ia[e] = head_agg[b * HH + e];
    else if (e < 2 * HH) ic[e - HH] = head_col[b * HH + (e - HH)];
    else if (e < 2 * HH + QQ) iq[e - 2 * HH] = quant_tab[b * QQ + (e - 2 * HH)];
    else if (e == 2 * HH + QQ) ib = box_op[b];
    __syncthreads();

    float he = 0.f;
#pragma unroll
    for (int h = 0; h < HH; h++)
        he += agg_emb[ia[h] * EE + e] + encoded_col[((size_t)b * NCc + ic[h]) * EE + e];
    he *= (1.0f / HH);
    float be = 0.f;
#pragma unroll
    for (int q = 0; q < QQ; q++)
        be += encoded_tab[((size_t)b * NTt + iq[q]) * EE + e];
    be *= (1.0f / QQ);

    float* boxA = g_boxA + (size_t)b * 3 * EE;
    boxA[e]          = he;
    boxA[EE + e]     = be;
    boxA[2 * EE + e] = box_op_emb[ib * EE + e];

    float* lA = g_lstmA + (size_t)b * 3 * EE;
    lA[EE + e]     = att[b * EE + e];
    lA[2 * EE + e] = h0[b * EE + e];
}

// ---------------- split-K register-blocked GEMM ----------------
// Computes partial C over k in [blockIdx.y*KC, (blockIdx.y+1)*KC) for a
// 32(batch) x 64(n) tile. part[(chunk*32 + b)*Ntot + n] = partial sum.
// W columns k<K1 from W1 (row stride K1), rest from W2 (row stride K-K1).
__global__ void gemm_splitk_kernel(const float* __restrict__ A, int K,
                                   const float* __restrict__ W1, int K1,
                                   const float* __restrict__ W2,
                                   float* __restrict__ part, int Ntot) {
    __shared__ float As[32][33];
    __shared__ float Ws[64][33];
    int tid = threadIdx.x;               // 256
    int n0  = blockIdx.x * 64;
    int KC  = K / gridDim.y;
    int kb  = blockIdx.y * KC;
    int tn  = tid & 15;                  // 4 n's each
    int tb  = tid >> 4;                  // b and b+16
    float acc[2][4] = {};
    int K2len = K - K1;

    for (int k0 = kb; k0 < kb + KC; k0 += 32) {
#pragma unroll
        for (int i = 0; i < 4; i++) {
            int idx = tid + i * 256;
            int r = idx >> 5, kk = idx & 31;
            As[r][kk] = A[(size_t)r * K + k0 + kk];
        }
#pragma unroll
        for (int i = 0; i < 8; i++) {
            int idx = tid + i * 256;
            int n = idx >> 5, kk = idx & 31;
            int kg = k0 + kk;
            float wv = (kg < K1) ? W1[(size_t)(n0 + n) * K1 + kg]
                                 : W2[(size_t)(n0 + n) * K2len + (kg - K1)];
            Ws[n][kk] = wv;
        }
        __syncthreads();
#pragma unroll
        for (int kk = 0; kk < 32; kk++) {
            float a0 = As[tb][kk];
            float a1 = As[tb + 16][kk];
#pragma unroll
            for (int j = 0; j < 4; j++) {
                float wv = Ws[tn * 4 + j][kk];
                acc[0][j] = fmaf(a0, wv, acc[0][j]);
                acc[1][j] = fmaf(a1, wv, acc[1][j]);
            }
        }
        __syncthreads();
    }
    float* dst = part + (size_t)(blockIdx.y * 32) * Ntot;
#pragma unroll
    for (int j = 0; j < 4; j++) {
        int n = n0 + tn * 4 + j;
        dst[(size_t)tb * Ntot + n]        = acc[0][j];
        dst[(size_t)(tb + 16) * Ntot + n] = acc[1][j];
    }
}

// ---------------- reduce split-K partials + bias (+relu) ----------------
__global__ void reduce_act_kernel(const float* __restrict__ part, int nchunks,
                                  int Ntot, const float* __restrict__ bias,
                                  float* __restrict__ out, int ldo, int relu) {
    int idx = blockIdx.x * blockDim.x + threadIdx.x;   // 32*Ntot
    int b = idx / Ntot, n = idx - b * Ntot;
    float s = 0.f;
    for (int c = 0; c < nchunks; c++)
        s += part[(size_t)(c * 32 + b) * Ntot + n];
    s += bias[n];
    if (relu) s = fmaxf(s, 0.f);
    out[(size_t)b * ldo + n] = s;
}

// ---------------- LSTM elementwise (reduces gates partials inline) ----------
__device__ __forceinline__ float sigmf(float x) { return 1.0f / (1.0f + expf(-x)); }

__global__ void lstm_elem_kernel(const float* __restrict__ c0,
                                 const float* __restrict__ b_ih,
                                 const float* __restrict__ b_hh) {
    int idx = blockIdx.x * blockDim.x + threadIdx.x;   // 32*512
    int b = idx >> 9, e = idx & 511;
    float gi = 0.f, gf = 0.f, gg = 0.f, go = 0.f;
#pragma unroll
    for (int c = 0; c < CH_GATES; c++) {
        const float* g = g_pgates + (size_t)(c * 32 + b) * 4 * EE;
        gi += g[e]; gf += g[EE + e]; gg += g[2 * EE + e]; go += g[3 * EE + e];
    }
    gi += b_ih[e]          + b_hh[e];
    gf += b_ih[EE + e]     + b_hh[EE + e];
    gg += b_ih[2 * EE + e] + b_hh[2 * EE + e];
    go += b_ih[3 * EE + e] + b_hh[3 * EE + e];
    float c = sigmf(gf) * c0[b * EE + e] + sigmf(gi) * tanhf(gg);
    float h = sigmf(go) * tanhf(c);
    g_hc[(size_t)b * 2 * EE + e] = h;
}

// ---------------- attention scores: warp per source row ----------------
__global__ void scores_kernel(const float* __restrict__ src_att,
                              const void* __restrict__ maskp) {
    int b = blockIdx.y;
    int tid = threadIdx.x;               // 256 = 8 warps
    __shared__ __align__(16) float sh[EE];
    for (int i = tid; i < EE; i += 256) sh[i] = g_hc[(size_t)b * 2 * EE + i];
    __syncthreads();

    int warp = tid >> 5, lane = tid & 31;
    int s = blockIdx.x * 8 + warp;
    const float4* row = (const float4*)(src_att + ((size_t)b * SS + s) * EE);
    const float4* h4  = (const float4*)sh;
    float4 v0 = row[lane +  0], h0v = h4[lane +  0];
    float4 v1 = row[lane + 32], h1v = h4[lane + 32];
    float4 v2 = row[lane + 64], h2v = h4[lane + 64];
    float4 v3 = row[lane + 96], h3v = h4[lane + 96];
    float a0 = v0.x * h0v.x + v0.y * h0v.y + v0.z * h0v.z + v0.w * h0v.w;
    float a1 = v1.x * h1v.x + v1.y * h1v.y + v1.z * h1v.z + v1.w * h1v.w;
    float a2 = v2.x * h2v.x + v2.y * h2v.y + v2.z * h2v.z + v2.w * h2v.w;
    float a3 = v3.x * h3v.x + v3.y * h3v.y + v3.z * h3v.z + v3.w * h3v.w;
    float acc = (a0 + a1) + (a2 + a3);
#pragma unroll
    for (int off = 16; off > 0; off >>= 1)
        acc += __shfl_xor_sync(0xFFFFFFFF, acc, off);

    if (lane == 0) {
        int mm = g_mask_mode;
        bool masked;
        size_t mi = (size_t)b * SS + s;
        if (mm == 0)      masked = ((const int*)maskp)[mi] != 0;
        else if (mm == 1) masked = ((const float*)maskp)[mi] != 0.f;
        else              masked = ((const unsigned char*)maskp)[mi] != 0;
        g_scores[mi] = masked ? -INFINITY : acc;
    }
}

// ---------------- softmax over S per batch row ----------------
__global__ void softmax_kernel() {
    int b = blockIdx.x;
    int tid = threadIdx.x;               // 256
    const float* sc = g_scores + (size_t)b * SS;
    __shared__ float red[256];
    float m = -INFINITY;
    for (int s = tid; s < SS; s += 256) m = fmaxf(m, sc[s]);
    red[tid] = m; __syncthreads();
    for (int o = 128; o > 0; o >>= 1) { if (tid < o) red[tid] = fmaxf(red[tid], red[tid + o]); __syncthreads(); }
    float mx = red[0]; __syncthreads();
    float sum = 0.f;
    for (int s = tid; s < SS; s += 256) sum += expf(sc[s] - mx);
    red[tid] = sum; __syncthreads();
    for (int o = 128; o > 0; o >>= 1) { if (tid < o) red[tid] += red[tid + o]; __syncthreads(); }
    float inv = 1.0f / red[0];
    float* w = g_attw + (size_t)b * SS;
    for (int s = tid; s < SS; s += 256) w[s] = expf(sc[s] - mx) * inv;
}

// ---------------- ctx partials: block per (chunk, b) ----------------
__global__ void ctx_part_kernel(const float* __restrict__ src) {
    int ch = blockIdx.x, b = blockIdx.y;
    int tid = threadIdx.x;               // 128, each owns float4 of E
    const int ROWS = SS / NCHUNK;        // 64
    __shared__ float w[ROWS];
    if (tid < ROWS) w[tid] = g_attw[(size_t)b * SS + ch * ROWS + tid];
    __syncthreads();
    const float4* base = (const float4*)(src + ((size_t)b * SS + (size_t)ch * ROWS) * EE);
    float4 acc = make_float4(0.f, 0.f, 0.f, 0.f);
#pragma unroll 8
    for (int s = 0; s < ROWS; s++) {
        float4 v = base[(size_t)s * 128 + tid];
        float ws = w[s];
        acc.x = fmaf(ws, v.x, acc.x);
        acc.y = fmaf(ws, v.y, acc.y);
        acc.z = fmaf(ws, v.z, acc.z);
        acc.w = fmaf(ws, v.w, acc.w);
    }
    ((float4*)g_part)[((size_t)b * NCHUNK + ch) * 128 + tid] = acc;
}

// ---------------- reduce ctx partials into g_hc[:, E:] ----------------
__global__ void ctx_reduce_kernel() {
    int idx = blockIdx.x * blockDim.x + threadIdx.x;   // 32*512
    int b = idx >> 9, e = idx & 511;
    float s = 0.f;
#pragma unroll
    for (int c = 0; c < NCHUNK; c++)
        s += g_part[((size_t)b * NCHUNK + c) * EE + e];
    g_hc[(size_t)b * 2 * EE + EE + e] = s;
}

// ---------------- launch ----------------
extern "C" void kernel_launch(void* const* d_in, const int* in_sizes, int n_in,
                              void* d_out, int out_size) {
    const float* encoded_src     = (const float*)d_in[0];
    const float* encoded_src_att = (const float*)d_in[1];
    const float* encoded_col     = (const float*)d_in[2];
    const float* encoded_tab     = (const float*)d_in[3];
    const void*  src_mask        = d_in[4];
    const float* att             = (const float*)d_in[5];
    const float* h0              = (const float*)d_in[6];
    const float* c0              = (const float*)d_in[7];
    const int*   head_agg        = (const int*)d_in[8];
    const int*   head_col        = (const int*)d_in[9];
    const int*   quant_tab       = (const int*)d_in[10];
    const int*   box_op          = (const int*)d_in[11];
    const float* agg_emb         = (const float*)d_in[12];
    const float* box_op_emb      = (const float*)d_in[13];
    const float* W_box           = (const float*)d_in[14];
    const float* b_box           = (const float*)d_in[15];
    const float* W_ih            = (const float*)d_in[16];
    const float* W_hh            = (const float*)d_in[17];
    const float* b_ih            = (const float*)d_in[18];
    const float* b_hh            = (const float*)d_in[19];
    const float* W_att           = (const float*)d_in[20];
    const float* b_att           = (const float*)d_in[21];
    float* out = (float*)d_out;

    float *p_boxA, *p_lstmA, *p_hc, *p_pbox, *p_pgates, *p_patt;
    cudaGetSymbolAddress((void**)&p_boxA, g_boxA);
    cudaGetSymbolAddress((void**)&p_lstmA, g_lstmA);
    cudaGetSymbolAddress((void**)&p_hc, g_hc);
    cudaGetSymbolAddress((void**)&p_pbox, g_pbox);
    cudaGetSymbolAddress((void**)&p_pgates, g_pgates);
    cudaGetSymbolAddress((void**)&p_patt, g_patt);

    // 1. sniff mask dtype (8KB scan)
    detect_mask_kernel<<<1, 256>>>((const unsigned int*)src_mask, 2048);

    // 2. gathers + concat prep
    prep_kernel<<<BB, EE>>>(agg_emb, encoded_col, encoded_tab, box_op_emb,
                            head_agg, head_col, quant_tab, box_op, att, h0);

    // 3. box GEMM: partials over 12 K-chunks (KC=128), grid 8x12
    gemm_splitk_kernel<<<dim3(EE / 64, CH_BOX), 256>>>(
        p_boxA, 3 * EE, W_box, 3 * EE, nullptr, p_pbox, EE);
    // 3b. reduce + bias + relu -> g_lstmA[:, :E]
    reduce_act_kernel<<<(BB * EE) / 256, 256>>>(p_pbox, CH_BOX, EE, b_box,
                                                p_lstmA, 3 * EE, 1);

    // 4. gates GEMM: [box|att|h0] @ [W_ih|W_hh]^T, grid 32x12
    gemm_splitk_kernel<<<dim3((4 * EE) / 64, CH_GATES), 256>>>(
        p_lstmA, 3 * EE, W_ih, 2 * EE, W_hh, p_pgates, 4 * EE);

    // 5. LSTM elementwise (reduces gate partials + biases) -> h in g_hc[:, :E]
    lstm_elem_kernel<<<(BB * EE) / 256, 256>>>(c0, b_ih, b_hh);

    // 6. attention scores (134 MB stream)
    scores_kernel<<<dim3(SS / 8, BB), 256>>>(encoded_src_att, src_mask);

    // 7. softmax
    softmax_kernel<<<BB, 256>>>();

    // 8. ctx partials (134 MB stream)
    ctx_part_kernel<<<dim3(NCHUNK, BB), 128>>>(encoded_src);

    // 9. reduce -> g_hc[:, E:]
    ctx_reduce_kernel<<<(BB * EE) / 256, 256>>>();

    // 10. att GEMM: [h|ctx] @ W_att^T, grid 8x16 (KC=64)
    gemm_splitk_kernel<<<dim3(EE / 64, CH_ATT), 256>>>(
        p_hc, 2 * EE, W_att, 2 * EE, nullptr, p_patt, EE);
    // 10b. reduce + bias + relu -> d_out
    reduce_act_kernel<<<(BB * EE) / 256, 256>>>(p_patt, CH_ATT, EE, b_att,
                                                out, EE, 1);
}